// round 17
// baseline (speedup 1.0000x reference)
#include <cuda_runtime.h>
#include <cuda_bf16.h>
#include <cstdint>

// Problem constants: N=100000, C=128, E=3200000
#define MAXN 100000
#define CH 128
#define MAXE 3200000
#define SCAN_CHUNK 1024

// Scratch (device globals -- no allocation allowed)
__device__ float g_deg[MAXN];
__device__ float g_dinv[MAXN];
__device__ int   g_cnt[MAXN];
__device__ int   g_start[MAXN + 1];
__device__ int   g_pos[MAXN];
__device__ int   g_bsum[SCAN_CHUNK];
__device__ int   g_esrc[MAXE];
__device__ float g_enrm[MAXE];
__device__ float g_h[(size_t)MAXN * CH];
__device__ float g_agg[(size_t)MAXN * CH];
__device__ float g_h2[(size_t)MAXN * CH];
__device__ uint32_t g_wsh[3][128 * 64];   // pre-split W hi (bf16x2, permuted)
__device__ uint32_t g_wsl[3][128 * 64];   // pre-split W lo

// ---------------------------------------------------------------------------
// helpers
// ---------------------------------------------------------------------------
// split two floats into packed bf16x2 hi + lo residual
__device__ __forceinline__ void split2(float v0, float v1, uint32_t& hi, uint32_t& lo) {
    __nv_bfloat162 h = __floats2bfloat162_rn(v0, v1);   // x=v0(low), y=v1(high)
    float h0 = __bfloat162float(h.x);
    float h1 = __bfloat162float(h.y);
    __nv_bfloat162 l = __floats2bfloat162_rn(v0 - h0, v1 - h1);
    hi = *(uint32_t*)&h;
    lo = *(uint32_t*)&l;
}

// permuted word position within a 32-word (64-col) chunk row:
// word w (= cols 2w,2w+1) -> pos so that pairs (kw, kw+4) are adjacent.
__device__ __forceinline__ int posw(int w) {
    return ((w >> 3) << 3) | ((w & 3) << 1) | ((w >> 2) & 1);
}

__device__ __forceinline__ void mma_bf16(float& c0, float& c1, float& c2, float& c3,
                                         uint32_t a0, uint32_t a1, uint32_t a2, uint32_t a3,
                                         uint32_t b0, uint32_t b1) {
    asm volatile(
        "mma.sync.aligned.m16n8k16.row.col.f32.bf16.bf16.f32 "
        "{%0,%1,%2,%3}, {%4,%5,%6,%7}, {%8,%9}, {%0,%1,%2,%3};"
        : "+f"(c0), "+f"(c1), "+f"(c2), "+f"(c3)
        : "r"(a0), "r"(a1), "r"(a2), "r"(a3), "r"(b0), "r"(b1));
}

// ---------------------------------------------------------------------------
// W pre-split: fp32 [128][128] -> bf16 hi/lo words in permuted chunk layout
// ---------------------------------------------------------------------------
__global__ void k_wsplit(const float* __restrict__ W,
                         uint32_t* __restrict__ wh, uint32_t* __restrict__ wl) {
    int idx = blockIdx.x * blockDim.x + threadIdx.x;   // 0 .. 128*64-1
    if (idx >= 128 * 64) return;
    int n = idx >> 6;
    int wg = idx & 63;          // global word 0..63
    int c = wg >> 5;            // chunk
    int w = wg & 31;            // word within chunk
    float v0 = W[n * CH + c * 64 + 2 * w];
    float v1 = W[n * CH + c * 64 + 2 * w + 1];
    uint32_t hi, lo;
    split2(v0, v1, hi, lo);
    int p = c * 32 + posw(w);
    wh[n * 64 + p] = hi;
    wl[n * 64 + p] = lo;
}

// ---------------------------------------------------------------------------
// bf16 mma.sync GEMM v2: K chunked (BK=64), permuted layout, LDS.64 frags,
// pre-split W from global. 2 CTAs/SM.  C = g( f(A)*W^T + bout )
// ---------------------------------------------------------------------------
#define SROW2 40                         // u32 stride per row (pad 8)
#define A_HI 0
#define A_LO (128 * SROW2)
#define W_HI (2 * 128 * SROW2)
#define W_LO (3 * 128 * SROW2)
#define GEMM_SMEM (4 * 128 * SROW2 * 4)  // 81920 bytes

template <bool RELU_IN, bool HAS_BOUT, bool RELU_OUT>
__global__ __launch_bounds__(256, 2) void k_gemm_mma(
    const float* __restrict__ A,
    const uint32_t* __restrict__ wh, const uint32_t* __restrict__ wl,
    const float* __restrict__ bin, const float* __restrict__ bout,
    float* __restrict__ C, int M)
{
    extern __shared__ uint32_t sm[];
    int tid = threadIdx.x;
    int row0 = blockIdx.x * 128;

    int wid = tid >> 5;
    int lane = tid & 31;
    int tq = lane >> 2;   // 0..7
    int tr = lane & 3;    // 0..3
    int mrow0 = (wid & 3) * 32;
    int ncol0 = (wid >> 2) * 64;

    float acc[2][8][4];
#pragma unroll
    for (int mt = 0; mt < 2; mt++)
#pragma unroll
        for (int nt = 0; nt < 8; nt++)
#pragma unroll
            for (int j = 0; j < 4; j++) acc[mt][nt][j] = 0.0f;

    int r = tid >> 1;               // 0..127 tile row (loader role)
    int half = tid & 1;             // 0/1 -> 32-col halves of the 64-col chunk
    int gr = row0 + r;
    int sbase = r * SROW2;

#pragma unroll
    for (int c = 0; c < 2; c++) {
        // ---- load A chunk (fp32 -> split, permuted scalar stores) ----
        {
            const float* arow = A + (size_t)gr * CH + c * 64 + half * 32;
#pragma unroll
            for (int i = 0; i < 8; i++) {
                float4 v = make_float4(0.f, 0.f, 0.f, 0.f);
                if (gr < M) v = *(const float4*)(arow + 4 * i);
                if (RELU_IN) {
                    float4 b = *(const float4*)(bin + c * 64 + half * 32 + 4 * i);
                    v.x = fmaxf(v.x + b.x, 0.f);
                    v.y = fmaxf(v.y + b.y, 0.f);
                    v.z = fmaxf(v.z + b.z, 0.f);
                    v.w = fmaxf(v.w + b.w, 0.f);
                }
                uint32_t h0, l0, h1, l1;
                split2(v.x, v.y, h0, l0);
                split2(v.z, v.w, h1, l1);
                int w0 = half * 16 + 2 * i;
                int p0 = posw(w0), p1 = posw(w0 + 1);
                sm[A_HI + sbase + p0] = h0;
                sm[A_HI + sbase + p1] = h1;
                sm[A_LO + sbase + p0] = l0;
                sm[A_LO + sbase + p1] = l1;
            }
        }
        // ---- load W chunk (pre-split, already permuted: uint4 copy) ----
        {
            const uint4* whp = (const uint4*)(wh + r * 64 + c * 32 + half * 16);
            const uint4* wlp = (const uint4*)(wl + r * 64 + c * 32 + half * 16);
#pragma unroll
            for (int i = 0; i < 4; i++) {
                *(uint4*)&sm[W_HI + sbase + half * 16 + 4 * i] = whp[i];
                *(uint4*)&sm[W_LO + sbase + half * 16 + 4 * i] = wlp[i];
            }
        }
        __syncthreads();

        // ---- compute this chunk: 4 k-steps of 16 ----
#pragma unroll
        for (int ksl = 0; ksl < 4; ksl++) {
            int kb = ksl * 8 + (tr << 1);
            uint2 ah0[2], ah1[2], al0[2], al1[2];
#pragma unroll
            for (int mt = 0; mt < 2; mt++) {
                int ra = (mrow0 + mt * 16 + tq) * SROW2 + kb;
                ah0[mt] = *(const uint2*)&sm[A_HI + ra];
                ah1[mt] = *(const uint2*)&sm[A_HI + ra + 8 * SROW2];
                al0[mt] = *(const uint2*)&sm[A_LO + ra];
                al1[mt] = *(const uint2*)&sm[A_LO + ra + 8 * SROW2];
            }
#pragma unroll
            for (int nt = 0; nt < 8; nt++) {
                int rb = (ncol0 + nt * 8 + tq) * SROW2 + kb;
                uint2 bh = *(const uint2*)&sm[W_HI + rb];
                uint2 bl = *(const uint2*)&sm[W_LO + rb];
#pragma unroll
                for (int mt = 0; mt < 2; mt++) {
                    mma_bf16(acc[mt][nt][0], acc[mt][nt][1], acc[mt][nt][2], acc[mt][nt][3],
                             ah0[mt].x, ah1[mt].x, ah0[mt].y, ah1[mt].y, bh.x, bh.y);
                    mma_bf16(acc[mt][nt][0], acc[mt][nt][1], acc[mt][nt][2], acc[mt][nt][3],
                             ah0[mt].x, ah1[mt].x, ah0[mt].y, ah1[mt].y, bl.x, bl.y);
                    mma_bf16(acc[mt][nt][0], acc[mt][nt][1], acc[mt][nt][2], acc[mt][nt][3],
                             al0[mt].x, al1[mt].x, al0[mt].y, al1[mt].y, bh.x, bh.y);
                }
            }
        }
        __syncthreads();
    }

    // ---- epilogue: direct stores with fused bias / relu ----
#pragma unroll
    for (int mt = 0; mt < 2; mt++) {
        int row = mrow0 + mt * 16 + tq;
        int gr0 = row0 + row;
        int gr1 = gr0 + 8;
#pragma unroll
        for (int nt = 0; nt < 8; nt++) {
            int col = ncol0 + nt * 8 + 2 * tr;
            float2 b = make_float2(0.f, 0.f);
            if (HAS_BOUT) b = *(const float2*)(bout + col);
            float2 o0, o1;
            o0.x = acc[mt][nt][0] + b.x;
            o0.y = acc[mt][nt][1] + b.y;
            o1.x = acc[mt][nt][2] + b.x;
            o1.y = acc[mt][nt][3] + b.y;
            if (RELU_OUT) {
                o0.x = fmaxf(o0.x, 0.f); o0.y = fmaxf(o0.y, 0.f);
                o1.x = fmaxf(o1.x, 0.f); o1.y = fmaxf(o1.y, 0.f);
            }
            if (gr0 < M) *(float2*)(C + (size_t)gr0 * CH + col) = o0;
            if (gr1 < M) *(float2*)(C + (size_t)gr1 * CH + col) = o1;
        }
    }
}

// ---------------------------------------------------------------------------
// graph preprocessing (unchanged, verified)
// ---------------------------------------------------------------------------
__global__ void k_init(int n) {
    int i = blockIdx.x * blockDim.x + threadIdx.x;
    if (i < n) { g_deg[i] = 1.0f; g_cnt[i] = 0; }
}

__global__ void k_hist(const int* __restrict__ dst,
                       const float* __restrict__ ew, int E) {
    int i = blockIdx.x * blockDim.x + threadIdx.x;
    if (i < E) {
        int d = dst[i];
        atomicAdd(&g_deg[d], ew[i]);
        atomicAdd(&g_cnt[d], 1);
    }
}

__global__ void k_dinv(int n) {
    int i = blockIdx.x * blockDim.x + threadIdx.x;
    if (i < n) {
        float d = g_deg[i];
        g_dinv[i] = (d > 0.0f) ? rsqrtf(d) : 0.0f;
    }
}

__global__ __launch_bounds__(SCAN_CHUNK) void k_scan1(int n) {
    __shared__ int s[SCAN_CHUNK];
    int i = blockIdx.x * SCAN_CHUNK + threadIdx.x;
    int v = (i < n) ? g_cnt[i] : 0;
    s[threadIdx.x] = v;
    __syncthreads();
#pragma unroll
    for (int off = 1; off < SCAN_CHUNK; off <<= 1) {
        int t = (threadIdx.x >= off) ? s[threadIdx.x - off] : 0;
        __syncthreads();
        s[threadIdx.x] += t;
        __syncthreads();
    }
    if (i < n) g_start[i] = s[threadIdx.x] - v;
    if (threadIdx.x == SCAN_CHUNK - 1) g_bsum[blockIdx.x] = s[SCAN_CHUNK - 1];
}

__global__ __launch_bounds__(SCAN_CHUNK) void k_scan2(int nblk) {
    __shared__ int s[SCAN_CHUNK];
    int v = (threadIdx.x < nblk) ? g_bsum[threadIdx.x] : 0;
    s[threadIdx.x] = v;
    __syncthreads();
#pragma unroll
    for (int off = 1; off < SCAN_CHUNK; off <<= 1) {
        int t = (threadIdx.x >= off) ? s[threadIdx.x - off] : 0;
        __syncthreads();
        s[threadIdx.x] += t;
        __syncthreads();
    }
    if (threadIdx.x < nblk) g_bsum[threadIdx.x] = s[threadIdx.x] - v;
}

__global__ void k_scan3(int n, int E) {
    int i = blockIdx.x * blockDim.x + threadIdx.x;
    if (i < n) {
        int st = g_start[i] + g_bsum[i / SCAN_CHUNK];
        g_start[i] = st;
        g_pos[i] = st;
    }
    if (i == 0) g_start[n] = E;
}

__global__ void k_bucket(const int* __restrict__ src,
                         const int* __restrict__ dst,
                         const float* __restrict__ ew, int E) {
    int i = blockIdx.x * blockDim.x + threadIdx.x;
    if (i < E) {
        int s = src[i];
        int d = dst[i];
        float nrm = g_dinv[s] * ew[i] * g_dinv[d];
        int p = atomicAdd(&g_pos[d], 1);
        g_esrc[p] = s;
        g_enrm[p] = nrm;
    }
}

__global__ __launch_bounds__(256) void k_agg(int n) {
    int lane = threadIdx.x & 31;
    int node = (blockIdx.x * blockDim.x + threadIdx.x) >> 5;
    if (node >= n) return;

    float di = g_dinv[node];
    float w2 = di * di;
    float4 acc = ((const float4*)(g_h + (size_t)node * CH))[lane];
    acc.x *= w2; acc.y *= w2; acc.z *= w2; acc.w *= w2;

    int beg = g_start[node];
    int end = g_start[node + 1];
    for (int e0 = beg; e0 < end; e0 += 32) {
        int m = end - e0;
        if (m > 32) m = 32;
        int   sv = 0;
        float nv = 0.0f;
        if (lane < m) { sv = g_esrc[e0 + lane]; nv = g_enrm[e0 + lane]; }
        for (int j = 0; j < m; j++) {
            int   sj = __shfl_sync(0xffffffffu, sv, j);
            float nj = __shfl_sync(0xffffffffu, nv, j);
            float4 v = ((const float4*)(g_h + (size_t)sj * CH))[lane];
            acc.x = fmaf(v.x, nj, acc.x);
            acc.y = fmaf(v.y, nj, acc.y);
            acc.z = fmaf(v.z, nj, acc.z);
            acc.w = fmaf(v.w, nj, acc.w);
        }
    }
    ((float4*)(g_agg + (size_t)node * CH))[lane] = acc;
}

// ---------------------------------------------------------------------------
// launch
// ---------------------------------------------------------------------------
extern "C" void kernel_launch(void* const* d_in, const int* in_sizes, int n_in,
                              void* d_out, int out_size) {
    const float* x   = (const float*)d_in[0];
    const int*   ei  = (const int*)d_in[1];    // int32 (JAX x64 disabled)
    const float* ew  = (const float*)d_in[2];
    const float* Wc  = (const float*)d_in[3];
    const float* bc  = (const float*)d_in[4];
    const float* Wf  = (const float*)d_in[5];
    const float* bf  = (const float*)d_in[6];
    const float* Wf2 = (const float*)d_in[7];
    const float* bf2 = (const float*)d_in[8];
    float*       out = (float*)d_out;

    int n = in_sizes[0] / CH;
    int E = in_sizes[2];
    const int* src = ei;
    const int* dst = ei + E;

    float *p_h, *p_agg, *p_h2;
    cudaGetSymbolAddress((void**)&p_h, g_h);
    cudaGetSymbolAddress((void**)&p_agg, g_agg);
    cudaGetSymbolAddress((void**)&p_h2, g_h2);
    uint32_t *p_wsh, *p_wsl;
    cudaGetSymbolAddress((void**)&p_wsh, g_wsh);
    cudaGetSymbolAddress((void**)&p_wsl, g_wsl);

    static bool attr_done = false;
    if (!attr_done) {
        cudaFuncSetAttribute(k_gemm_mma<false, false, false>,
                             cudaFuncAttributeMaxDynamicSharedMemorySize, GEMM_SMEM);
        cudaFuncSetAttribute(k_gemm_mma<true, true, true>,
                             cudaFuncAttributeMaxDynamicSharedMemorySize, GEMM_SMEM);
        cudaFuncSetAttribute(k_gemm_mma<false, true, false>,
                             cudaFuncAttributeMaxDynamicSharedMemorySize, GEMM_SMEM);
        attr_done = true;
    }

    int nblk = (n + SCAN_CHUNK - 1) / SCAN_CHUNK;

    // 0. pre-split weights (independent of everything else)
    k_wsplit<<<32, 256>>>(Wc,  p_wsh + 0 * 8192, p_wsl + 0 * 8192);
    k_wsplit<<<32, 256>>>(Wf,  p_wsh + 1 * 8192, p_wsl + 1 * 8192);
    k_wsplit<<<32, 256>>>(Wf2, p_wsh + 2 * 8192, p_wsl + 2 * 8192);

    // 1. degree + histogram, dinv
    k_init<<<(n + 255) / 256, 256>>>(n);
    k_hist<<<(E + 255) / 256, 256>>>(dst, ew, E);
    k_dinv<<<(n + 255) / 256, 256>>>(n);

    // 2. exclusive scan -> CSR offsets
    k_scan1<<<nblk, SCAN_CHUNK>>>(n);
    k_scan2<<<1, SCAN_CHUNK>>>(nblk);
    k_scan3<<<(n + 255) / 256, 256>>>(n, E);

    // 3. h = x @ Wc^T
    int gb = (n + 127) / 128;
    k_gemm_mma<false, false, false><<<gb, 256, GEMM_SMEM>>>(
        x, p_wsh + 0 * 8192, p_wsl + 0 * 8192, nullptr, nullptr, p_h, n);

    // 4. bucket edges by dst
    k_bucket<<<(E + 255) / 256, 256>>>(src, dst, ew, E);

    // 5. gather-only aggregation
    k_agg<<<(n * 32 + 255) / 256, 256>>>(n);

    // 6. h2 = relu(relu(agg + bc) @ Wf^T + bf)
    k_gemm_mma<true, true, true><<<gb, 256, GEMM_SMEM>>>(
        p_agg, p_wsh + 1 * 8192, p_wsl + 1 * 8192, bc, bf, p_h2, n);

    // 7. out = h2 @ Wf2^T + bf2
    k_gemm_mma<false, true, false><<<gb, 256, GEMM_SMEM>>>(
        p_h2, p_wsh + 2 * 8192, p_wsl + 2 * 8192, nullptr, bf2, out, n);
}